// round 1
// baseline (speedup 1.0000x reference)
#include <cuda_runtime.h>

#define MAXL 2048
#define TILE 256
#define FR_STRIDE 24

// Scratch (no allocations allowed): frame table, pair list, accumulators.
__device__ float  g_frames[3 * MAXL * FR_STRIDE];
__device__ int    g_pairs[2 * MAXL];
__device__ int    g_K;
__device__ double g_S[2];

__device__ __forceinline__ float fast_sqrtf(float x) {
    float r;
    asm("sqrt.approx.f32 %0, %1;" : "=f"(r) : "f"(x));
    return r;
}

// rigid_from_3points: a = 9 floats (x1,x2,x3 atoms). R row-major (rows e1,e2,e3), t = x2.
__device__ __forceinline__ void rigid3(const float* __restrict__ a, float R[9], float t[3]) {
    float x1x = a[0], x1y = a[1], x1z = a[2];
    float x2x = a[3], x2y = a[4], x2z = a[5];
    float x3x = a[6], x3y = a[7], x3z = a[8];
    float v1x = x3x - x2x, v1y = x3y - x2y, v1z = x3z - x2z;
    float v2x = x1x - x2x, v2y = x1y - x2y, v2z = x1z - x2z;
    float n1 = fast_sqrtf(fmaf(v1x, v1x, fmaf(v1y, v1y, v1z * v1z)));
    float inv1 = __fdividef(1.0f, n1 + 0.001f);
    float e1x = v1x * inv1, e1y = v1y * inv1, e1z = v1z * inv1;
    float d12 = fmaf(e1x, v2x, fmaf(e1y, v2y, e1z * v2z));
    float u2x = fmaf(-e1x, d12, v2x);
    float u2y = fmaf(-e1y, d12, v2y);
    float u2z = fmaf(-e1z, d12, v2z);
    float n2 = fast_sqrtf(fmaf(u2x, u2x, fmaf(u2y, u2y, u2z * u2z)));
    float inv2 = __fdividef(1.0f, n2 + 1e-8f);
    float e2x = u2x * inv2, e2y = u2y * inv2, e2z = u2z * inv2;
    // e3 = e1 x e2
    float e3x = e1y * e2z - e1z * e2y;
    float e3y = e1z * e2x - e1x * e2z;
    float e3z = e1x * e2y - e1y * e2x;
    R[0] = e1x; R[1] = e1y; R[2] = e1z;
    R[3] = e2x; R[4] = e2y; R[5] = e2z;
    R[6] = e3x; R[7] = e3y; R[8] = e3z;
    t[0] = x2x; t[1] = x2y; t[2] = x2z;
}

__global__ void k_init() {
    g_K = 0;
    g_S[0] = 0.0;
    g_S[1] = 0.0;
}

// One warp per row: find the smallest j > row with m[row][j] != 0 (triu + first-per-row).
// Order of compaction is irrelevant: the pair frames enter an order-free mean.
__global__ void k_pairs(const int* __restrict__ m, int L) {
    int warp = (blockIdx.x * blockDim.x + threadIdx.x) >> 5;
    int lane = threadIdx.x & 31;
    if (warp >= L) return;
    const int* row = m + (long long)warp * L;
    for (int base = warp + 1; base < L; base += 32) {
        int j = base + lane;
        bool nz = (j < L) && (row[j] != 0);
        unsigned b = __ballot_sync(0xffffffffu, nz);
        if (b) {
            if (lane == 0) {
                int jj = base + __ffs(b) - 1;
                int s = atomicAdd(&g_K, 1);
                g_pairs[2 * s] = warp;
                g_pairs[2 * s + 1] = jj;
            }
            return;
        }
    }
}

// Build precomposed frame table.
//   t in [0, L)      : term1  — pred = given (p_rot, p_tran), true = rigid(target[i]), clamp 40
//   t in [L, 2L)     : term2a — pred = rigid(coor[i]),         true = rigid(target[i]), clamp 5
//   t in [2L, 2L+K)  : term2b — midpoint frames of pair (i,j), clamp 5
// Record: Rp[9], -Rt[9], c[3] (= Rp*tp - Rt*tt), clamp^2, pad[2]  (stride 24)
__global__ void k_frames(const float* __restrict__ coor,
                         const float* __restrict__ prot,
                         const float* __restrict__ ptran,
                         const float* __restrict__ target, int L) {
    int t = blockIdx.x * blockDim.x + threadIdx.x;
    int K = g_K;
    if (t >= 2 * L + K) return;

    float Rp[9], tp[3], Rt[9], tt[3], clampv;
    if (t < L) {
        #pragma unroll
        for (int i = 0; i < 9; i++) Rp[i] = prot[t * 9 + i];
        tp[0] = ptran[t * 3 + 0];
        tp[1] = ptran[t * 3 + 1];
        tp[2] = ptran[t * 3 + 2];
        rigid3(target + t * 9, Rt, tt);
        clampv = 40.0f;
    } else if (t < 2 * L) {
        int i = t - L;
        rigid3(coor + i * 9, Rp, tp);
        rigid3(target + i * 9, Rt, tt);
        clampv = 5.0f;
    } else {
        int k = t - 2 * L;
        int i = g_pairs[2 * k], j = g_pairs[2 * k + 1];
        float mc[9], mt[9];
        #pragma unroll
        for (int q = 0; q < 9; q++) {
            mc[q] = 0.5f * (coor[i * 9 + q] + coor[j * 9 + q]);
            mt[q] = 0.5f * (target[i * 9 + q] + target[j * 9 + q]);
        }
        rigid3(mc, Rp, tp);
        rigid3(mt, Rt, tt);
        clampv = 5.0f;
    }

    float* o = g_frames + t * FR_STRIDE;
    #pragma unroll
    for (int i = 0; i < 9; i++) o[i] = Rp[i];
    #pragma unroll
    for (int i = 0; i < 9; i++) o[9 + i] = -Rt[i];
    #pragma unroll
    for (int k = 0; k < 3; k++) {
        float cp = fmaf(Rp[3 * k], tp[0], fmaf(Rp[3 * k + 1], tp[1], Rp[3 * k + 2] * tp[2]));
        float ct = fmaf(Rt[3 * k], tt[0], fmaf(Rt[3 * k + 1], tt[1], Rt[3 * k + 2] * tt[2]));
        o[18 + k] = cp - ct;
    }
    o[21] = clampv * clampv;
    o[22] = 0.0f;
    o[23] = 0.0f;
}

// Main FAPE kernel: thread = frame, block = 256 frames x TILE points.
// grid.x = point chunk, grid.y = frame group.
__global__ void __launch_bounds__(256) k_main(const float* __restrict__ coor,
                                              const float* __restrict__ target, int L) {
    __shared__ float sp[TILE * 8];  // per point: {x0,x1,x2,y0,y1,y2,pad,pad}
    __shared__ float r0s[8], r1s[8];

    int K = g_K;
    int nframes = 2 * L + K;
    int frame = blockIdx.y * 256 + threadIdx.x;
    int P = 3 * L;
    int p0 = blockIdx.x * TILE;
    int npt = P - p0;
    if (npt > TILE) npt = TILE;

    // Skip fully-inactive frame groups (frames beyond 2L+K).
    if (blockIdx.y * 256 >= nframes) return;

    for (int idx = threadIdx.x; idx < npt * 8; idx += 256) {
        int p = idx >> 3, d = idx & 7;
        float v = 0.0f;
        int g = (p0 + p) * 3;
        if (d < 3) v = coor[g + d];
        else if (d < 6) v = target[g + d - 3];
        sp[idx] = v;
    }
    __syncthreads();

    float acc = 0.0f;
    if (frame < nframes) {
        const float* f = g_frames + frame * FR_STRIDE;
        float a0 = f[0], a1 = f[1], a2 = f[2], a3 = f[3], a4 = f[4];
        float a5 = f[5], a6 = f[6], a7 = f[7], a8 = f[8];
        float b0 = f[9], b1 = f[10], b2 = f[11], b3 = f[12], b4 = f[13];
        float b5 = f[14], b6 = f[15], b7 = f[16], b8 = f[17];
        float c0 = f[18], c1 = f[19], c2 = f[20], csq = f[21];

        const float4* sp4 = (const float4*)sp;
        #pragma unroll 4
        for (int p = 0; p < npt; ++p) {
            float4 u = sp4[2 * p];
            float4 w = sp4[2 * p + 1];
            float x0 = u.x, x1 = u.y, x2 = u.z, y0 = u.w, y1 = w.x, y2 = w.y;
            float d0 = fmaf(a0, x0, fmaf(a1, x1, fmaf(a2, x2,
                       fmaf(b0, y0, fmaf(b1, y1, fmaf(b2, y2, -c0))))));
            float d1 = fmaf(a3, x0, fmaf(a4, x1, fmaf(a5, x2,
                       fmaf(b3, y0, fmaf(b4, y1, fmaf(b5, y2, -c1))))));
            float d2 = fmaf(a6, x0, fmaf(a7, x1, fmaf(a8, x2,
                       fmaf(b6, y0, fmaf(b7, y1, fmaf(b8, y2, -c2))))));
            float s = fmaf(d0, d0, fmaf(d1, d1, fmaf(d2, d2, 0.001f)));
            s = fminf(s, csq);
            acc += fast_sqrtf(s);
        }
    }

    // Split into term1 (frame < L) / term2 accumulators; block homogeneous in the common
    // case, but keep it general.
    float acc0 = (frame < L) ? acc : 0.0f;
    float acc1 = (frame < L) ? 0.0f : acc;
    #pragma unroll
    for (int o = 16; o; o >>= 1) {
        acc0 += __shfl_down_sync(0xffffffffu, acc0, o);
        acc1 += __shfl_down_sync(0xffffffffu, acc1, o);
    }
    int w = threadIdx.x >> 5, l = threadIdx.x & 31;
    if (l == 0) { r0s[w] = acc0; r1s[w] = acc1; }
    __syncthreads();
    if (threadIdx.x == 0) {
        float s0 = 0.0f, s1 = 0.0f;
        #pragma unroll
        for (int i = 0; i < 8; i++) { s0 += r0s[i]; s1 += r1s[i]; }
        if (s0 != 0.0f) atomicAdd(&g_S[0], (double)s0);
        if (s1 != 0.0f) atomicAdd(&g_S[1], (double)s1);
    }
}

__global__ void k_final(float* out, int L) {
    double P = 3.0 * (double)L;
    double res = g_S[0] / ((double)L * P);
    int K = g_K;
    if (K > 0) res += g_S[1] / ((double)(L + K) * P);
    out[0] = (float)(res * 0.1);
}

extern "C" void kernel_launch(void* const* d_in, const int* in_sizes, int n_in,
                              void* d_out, int out_size) {
    const float* coor   = (const float*)d_in[0];
    const float* prot   = (const float*)d_in[1];
    const float* ptran  = (const float*)d_in[2];
    const float* target = (const float*)d_in[3];
    const int*   matrix = (const int*)d_in[4];

    int L = in_sizes[0] / 9;
    int P = 3 * L;
    int maxFrames = 3 * L;  // 2L + K, K <= L

    k_init<<<1, 1>>>();
    k_pairs<<<(L + 7) / 8, 256>>>(matrix, L);
    k_frames<<<(maxFrames + 255) / 256, 256>>>(coor, prot, ptran, target, L);
    dim3 grid((P + TILE - 1) / TILE, (maxFrames + 255) / 256);
    k_main<<<grid, 256>>>(coor, target, L);
    k_final<<<1, 1>>>((float*)d_out, L);
}

// round 2
// speedup vs baseline: 1.4160x; 1.4160x over previous
#include <cuda_runtime.h>

#define MAXL 2048
#define TILE 256
#define FR_STRIDE 24

typedef unsigned long long u64;

// Scratch (no allocations allowed): frame table, pair list, accumulators.
__device__ float  g_frames[3 * MAXL * FR_STRIDE];
__device__ int    g_pairs[2 * MAXL];
__device__ int    g_K;
__device__ double g_S[2];

__device__ __forceinline__ float fast_sqrtf(float x) {
    float r;
    asm("sqrt.approx.f32 %0, %1;" : "=f"(r) : "f"(x));
    return r;
}

// ---- packed f32x2 helpers (Blackwell; FFMA2 only reachable via PTX) ----
__device__ __forceinline__ u64 pk2(float lo, float hi) {
    u64 r;
    asm("mov.b64 %0, {%1, %2};" : "=l"(r) : "f"(lo), "f"(hi));
    return r;
}
__device__ __forceinline__ void upk2(float& lo, float& hi, u64 v) {
    asm("mov.b64 {%0, %1}, %2;" : "=f"(lo), "=f"(hi) : "l"(v));
}
__device__ __forceinline__ u64 fma2(u64 a, u64 b, u64 c) {
    u64 d;
    asm("fma.rn.f32x2 %0, %1, %2, %3;" : "=l"(d) : "l"(a), "l"(b), "l"(c));
    return d;
}

// rigid_from_3points: a = 9 floats (x1,x2,x3 atoms). R row-major (rows e1,e2,e3), t = x2.
__device__ __forceinline__ void rigid3(const float* __restrict__ a, float R[9], float t[3]) {
    float x1x = a[0], x1y = a[1], x1z = a[2];
    float x2x = a[3], x2y = a[4], x2z = a[5];
    float x3x = a[6], x3y = a[7], x3z = a[8];
    float v1x = x3x - x2x, v1y = x3y - x2y, v1z = x3z - x2z;
    float v2x = x1x - x2x, v2y = x1y - x2y, v2z = x1z - x2z;
    float n1 = fast_sqrtf(fmaf(v1x, v1x, fmaf(v1y, v1y, v1z * v1z)));
    float inv1 = __fdividef(1.0f, n1 + 0.001f);
    float e1x = v1x * inv1, e1y = v1y * inv1, e1z = v1z * inv1;
    float d12 = fmaf(e1x, v2x, fmaf(e1y, v2y, e1z * v2z));
    float u2x = fmaf(-e1x, d12, v2x);
    float u2y = fmaf(-e1y, d12, v2y);
    float u2z = fmaf(-e1z, d12, v2z);
    float n2 = fast_sqrtf(fmaf(u2x, u2x, fmaf(u2y, u2y, u2z * u2z)));
    float inv2 = __fdividef(1.0f, n2 + 1e-8f);
    float e2x = u2x * inv2, e2y = u2y * inv2, e2z = u2z * inv2;
    float e3x = e1y * e2z - e1z * e2y;
    float e3y = e1z * e2x - e1x * e2z;
    float e3z = e1x * e2y - e1y * e2x;
    R[0] = e1x; R[1] = e1y; R[2] = e1z;
    R[3] = e2x; R[4] = e2y; R[5] = e2z;
    R[6] = e3x; R[7] = e3y; R[8] = e3z;
    t[0] = x2x; t[1] = x2y; t[2] = x2z;
}

__global__ void k_init() {
    g_K = 0;
    g_S[0] = 0.0;
    g_S[1] = 0.0;
}

// One warp per row, FULL scan with int4 loads (MLP=16, no serial early-exit):
// find the smallest j > row with m[row][j] != 0. Order of compaction slots is
// irrelevant (pair frames enter an order-free mean).
__global__ void k_pairs(const int* __restrict__ m, int L) {
    int row = (blockIdx.x * blockDim.x + threadIdx.x) >> 5;
    int lane = threadIdx.x & 31;
    if (row >= L) return;
    const int* rp = m + (long long)row * L;
    const int4* r4 = (const int4*)rp;
    int n4 = L >> 2;
    int best = 0x7fffffff;
    for (int t = lane; t < n4; t += 32) {
        int4 v = __ldg(&r4[t]);
        int c = t << 2;
        if (v.x != 0 && c     > row) best = min(best, c);
        if (v.y != 0 && c + 1 > row) best = min(best, c + 1);
        if (v.z != 0 && c + 2 > row) best = min(best, c + 2);
        if (v.w != 0 && c + 3 > row) best = min(best, c + 3);
    }
    for (int j = (n4 << 2) + lane; j < L; j += 32) {   // L%4 tail (none for L=2048)
        if (rp[j] != 0 && j > row) best = min(best, j);
    }
    #pragma unroll
    for (int o = 16; o; o >>= 1) best = min(best, __shfl_xor_sync(0xffffffffu, best, o));
    if (lane == 0 && best != 0x7fffffff) {
        int s = atomicAdd(&g_K, 1);
        g_pairs[2 * s]     = row;
        g_pairs[2 * s + 1] = best;
    }
}

// Build precomposed frame table.
//   t in [0, L)      : term1  — pred = given (p_rot, p_tran), true = rigid(target[i]), clamp 40
//   t in [L, 2L)     : term2a — pred = rigid(coor[i]),         true = rigid(target[i]), clamp 5
//   t in [2L, 2L+K)  : term2b — midpoint frames of pair (i,j), clamp 5
// Record: Rp[9], -Rt[9], c[3] (= Rt*tt - Rp*tp, i.e. ADDITIVE const), clamp^2, pad[2]
__global__ void k_frames(const float* __restrict__ coor,
                         const float* __restrict__ prot,
                         const float* __restrict__ ptran,
                         const float* __restrict__ target, int L) {
    int t = blockIdx.x * blockDim.x + threadIdx.x;
    int K = g_K;
    if (t >= 2 * L + K) return;

    float Rp[9], tp[3], Rt[9], tt[3], clampv;
    if (t < L) {
        #pragma unroll
        for (int i = 0; i < 9; i++) Rp[i] = prot[t * 9 + i];
        tp[0] = ptran[t * 3 + 0];
        tp[1] = ptran[t * 3 + 1];
        tp[2] = ptran[t * 3 + 2];
        rigid3(target + t * 9, Rt, tt);
        clampv = 40.0f;
    } else if (t < 2 * L) {
        int i = t - L;
        rigid3(coor + i * 9, Rp, tp);
        rigid3(target + i * 9, Rt, tt);
        clampv = 5.0f;
    } else {
        int k = t - 2 * L;
        int i = g_pairs[2 * k], j = g_pairs[2 * k + 1];
        float mc[9], mt[9];
        #pragma unroll
        for (int q = 0; q < 9; q++) {
            mc[q] = 0.5f * (coor[i * 9 + q] + coor[j * 9 + q]);
            mt[q] = 0.5f * (target[i * 9 + q] + target[j * 9 + q]);
        }
        rigid3(mc, Rp, tp);
        rigid3(mt, Rt, tt);
        clampv = 5.0f;
    }

    float* o = g_frames + t * FR_STRIDE;
    #pragma unroll
    for (int i = 0; i < 9; i++) o[i] = Rp[i];
    #pragma unroll
    for (int i = 0; i < 9; i++) o[9 + i] = -Rt[i];
    #pragma unroll
    for (int k = 0; k < 3; k++) {
        float cp = fmaf(Rp[3 * k], tp[0], fmaf(Rp[3 * k + 1], tp[1], Rp[3 * k + 2] * tp[2]));
        float ct = fmaf(Rt[3 * k], tt[0], fmaf(Rt[3 * k + 1], tt[1], Rt[3 * k + 2] * tt[2]));
        o[18 + k] = ct - cp;   // additive constant
    }
    o[21] = clampv * clampv;
    o[22] = 0.0f;
    o[23] = 0.0f;
}

// Main FAPE kernel, packed f32x2 over point-PAIRS.
// thread = frame (128 frames per block), smem tile = TILE points, pair-interleaved:
//   sp[q*12 + d*2 + lane]  for pair q, dim d in {x0,x1,x2,y0,y1,y2}, lane = point parity.
__global__ void __launch_bounds__(128) k_main(const float* __restrict__ coor,
                                              const float* __restrict__ target, int L) {
    __shared__ __align__(16) float sp[TILE * 6];
    __shared__ float r0s[4], r1s[4];

    int K = g_K;
    int nframes = 2 * L + K;
    if (blockIdx.y * 128 >= nframes) return;   // fully-dead frame group
    int frame = blockIdx.y * 128 + threadIdx.x;
    int P = 3 * L;
    int p0 = blockIdx.x * TILE;
    int npt = P - p0;
    if (npt > TILE) npt = TILE;

    // Fill tile: contiguous reads of coor/target, pair-interleaved writes.
    for (int idx = threadIdx.x; idx < TILE * 3; idx += 128) {
        float vc = 0.0f, vt = 0.0f;
        if (idx < npt * 3) {
            vc = coor[p0 * 3 + idx];
            vt = target[p0 * 3 + idx];
        }
        int p = idx / 3, d = idx - 3 * p;
        int q = p >> 1, ln = p & 1;
        sp[q * 12 + d * 2 + ln]       = vc;
        sp[q * 12 + (d + 3) * 2 + ln] = vt;
    }
    __syncthreads();

    float acc = 0.0f;
    if (frame < nframes) {
        const float* f = g_frames + frame * FR_STRIDE;
        float a0 = f[0], a1 = f[1], a2 = f[2], a3 = f[3], a4 = f[4];
        float a5 = f[5], a6 = f[6], a7 = f[7], a8 = f[8];
        float b0 = f[9], b1 = f[10], b2 = f[11], b3 = f[12], b4 = f[13];
        float b5 = f[14], b6 = f[15], b7 = f[16], b8 = f[17];
        float c0 = f[18], c1 = f[19], c2 = f[20], csq = f[21];

        // Pack frame constants (replicated lanes) once.
        u64 A0 = pk2(a0, a0), A1 = pk2(a1, a1), A2 = pk2(a2, a2);
        u64 A3 = pk2(a3, a3), A4 = pk2(a4, a4), A5 = pk2(a5, a5);
        u64 A6 = pk2(a6, a6), A7 = pk2(a7, a7), A8 = pk2(a8, a8);
        u64 B0 = pk2(b0, b0), B1 = pk2(b1, b1), B2 = pk2(b2, b2);
        u64 B3 = pk2(b3, b3), B4 = pk2(b4, b4), B5 = pk2(b5, b5);
        u64 B6 = pk2(b6, b6), B7 = pk2(b7, b7), B8 = pk2(b8, b8);
        u64 C0 = pk2(c0, c0), C1 = pk2(c1, c1), C2 = pk2(c2, c2);
        u64 EP2 = pk2(0.001f, 0.001f);

        const ulonglong2* sv = (const ulonglong2*)sp;
        int nq = npt >> 1;
        float accL = 0.0f, accH = 0.0f;
        #pragma unroll 4
        for (int q = 0; q < nq; ++q) {
            ulonglong2 v0 = sv[q * 3 + 0];   // {X0, X1}
            ulonglong2 v1 = sv[q * 3 + 1];   // {X2, Y0}
            ulonglong2 v2 = sv[q * 3 + 2];   // {Y1, Y2}
            u64 D0 = fma2(A0, v0.x, fma2(A1, v0.y, fma2(A2, v1.x,
                     fma2(B0, v1.y, fma2(B1, v2.x, fma2(B2, v2.y, C0))))));
            u64 D1 = fma2(A3, v0.x, fma2(A4, v0.y, fma2(A5, v1.x,
                     fma2(B3, v1.y, fma2(B4, v2.x, fma2(B5, v2.y, C1))))));
            u64 D2 = fma2(A6, v0.x, fma2(A7, v0.y, fma2(A8, v1.x,
                     fma2(B6, v1.y, fma2(B7, v2.x, fma2(B8, v2.y, C2))))));
            u64 S = fma2(D0, D0, fma2(D1, D1, fma2(D2, D2, EP2)));
            float sl, sh;
            upk2(sl, sh, S);
            sl = fminf(sl, csq);
            sh = fminf(sh, csq);
            accL += fast_sqrtf(sl);
            accH += fast_sqrtf(sh);
        }
        acc = accL + accH;
        if (npt & 1) {   // scalar tail point (never taken for P%TILE==0)
            const float* pt = sp + (nq * 12);
            float x0 = pt[0], x1 = pt[2], x2 = pt[4], y0 = pt[6], y1 = pt[8], y2 = pt[10];
            float d0 = fmaf(a0, x0, fmaf(a1, x1, fmaf(a2, x2,
                       fmaf(b0, y0, fmaf(b1, y1, fmaf(b2, y2, c0))))));
            float d1 = fmaf(a3, x0, fmaf(a4, x1, fmaf(a5, x2,
                       fmaf(b3, y0, fmaf(b4, y1, fmaf(b5, y2, c1))))));
            float d2 = fmaf(a6, x0, fmaf(a7, x1, fmaf(a8, x2,
                       fmaf(b6, y0, fmaf(b7, y1, fmaf(b8, y2, c2))))));
            float s = fmaf(d0, d0, fmaf(d1, d1, fmaf(d2, d2, 0.001f)));
            acc += fast_sqrtf(fminf(s, csq));
        }
    }

    float acc0 = (frame < L) ? acc : 0.0f;
    float acc1 = (frame < L) ? 0.0f : acc;
    #pragma unroll
    for (int o = 16; o; o >>= 1) {
        acc0 += __shfl_down_sync(0xffffffffu, acc0, o);
        acc1 += __shfl_down_sync(0xffffffffu, acc1, o);
    }
    int w = threadIdx.x >> 5, l = threadIdx.x & 31;
    if (l == 0) { r0s[w] = acc0; r1s[w] = acc1; }
    __syncthreads();
    if (threadIdx.x == 0) {
        float s0 = r0s[0] + r0s[1] + r0s[2] + r0s[3];
        float s1 = r1s[0] + r1s[1] + r1s[2] + r1s[3];
        if (s0 != 0.0f) atomicAdd(&g_S[0], (double)s0);
        if (s1 != 0.0f) atomicAdd(&g_S[1], (double)s1);
    }
}

__global__ void k_final(float* out, int L) {
    double P = 3.0 * (double)L;
    double res = g_S[0] / ((double)L * P);
    int K = g_K;
    if (K > 0) res += g_S[1] / ((double)(L + K) * P);
    out[0] = (float)(res * 0.1);
}

extern "C" void kernel_launch(void* const* d_in, const int* in_sizes, int n_in,
                              void* d_out, int out_size) {
    const float* coor   = (const float*)d_in[0];
    const float* prot   = (const float*)d_in[1];
    const float* ptran  = (const float*)d_in[2];
    const float* target = (const float*)d_in[3];
    const int*   matrix = (const int*)d_in[4];

    int L = in_sizes[0] / 9;
    int P = 3 * L;
    int maxFrames = 3 * L;   // 2L + K, K <= L

    k_init<<<1, 1>>>();
    k_pairs<<<(L * 32 + 255) / 256, 256>>>(matrix, L);
    k_frames<<<(maxFrames + 255) / 256, 256>>>(coor, prot, ptran, target, L);
    dim3 grid((P + TILE - 1) / TILE, (maxFrames + 127) / 128);
    k_main<<<grid, 128>>>(coor, target, L);
    k_final<<<1, 1>>>((float*)d_out, L);
}

// round 3
// speedup vs baseline: 1.7319x; 1.2231x over previous
#include <cuda_runtime.h>

#define MAXL 2048
#define TILE 256
#define FR_STRIDE 16

typedef unsigned long long u64;

// Scratch (no allocations allowed): frame table, pair list, accumulators.
__device__ float  g_frames[3 * MAXL * FR_STRIDE];
__device__ int    g_pairs[2 * MAXL];
__device__ int    g_K;
__device__ double g_S[2];

__device__ __forceinline__ float fast_sqrtf(float x) {
    float r;
    asm("sqrt.approx.f32 %0, %1;" : "=f"(r) : "f"(x));
    return r;
}

// ---- packed f32x2 helpers (FFMA2/FADD2 only reachable via PTX) ----
__device__ __forceinline__ u64 pk2(float lo, float hi) {
    u64 r;
    asm("mov.b64 %0, {%1, %2};" : "=l"(r) : "f"(lo), "f"(hi));
    return r;
}
__device__ __forceinline__ void upk2(float& lo, float& hi, u64 v) {
    asm("mov.b64 {%0, %1}, %2;" : "=f"(lo), "=f"(hi) : "l"(v));
}
__device__ __forceinline__ u64 fma2(u64 a, u64 b, u64 c) {
    u64 d;
    asm("fma.rn.f32x2 %0, %1, %2, %3;" : "=l"(d) : "l"(a), "l"(b), "l"(c));
    return d;
}
__device__ __forceinline__ u64 add2(u64 a, u64 b) {
    u64 d;
    asm("add.rn.f32x2 %0, %1, %2;" : "=l"(d) : "l"(a), "l"(b));
    return d;
}

// rigid_from_3points: a = 9 floats (x1,x2,x3 atoms). R row-major (rows e1,e2,e3), t = x2.
__device__ __forceinline__ void rigid3(const float* __restrict__ a, float R[9], float t[3]) {
    float x1x = a[0], x1y = a[1], x1z = a[2];
    float x2x = a[3], x2y = a[4], x2z = a[5];
    float x3x = a[6], x3y = a[7], x3z = a[8];
    float v1x = x3x - x2x, v1y = x3y - x2y, v1z = x3z - x2z;
    float v2x = x1x - x2x, v2y = x1y - x2y, v2z = x1z - x2z;
    float n1 = fast_sqrtf(fmaf(v1x, v1x, fmaf(v1y, v1y, v1z * v1z)));
    float inv1 = __fdividef(1.0f, n1 + 0.001f);
    float e1x = v1x * inv1, e1y = v1y * inv1, e1z = v1z * inv1;
    float d12 = fmaf(e1x, v2x, fmaf(e1y, v2y, e1z * v2z));
    float u2x = fmaf(-e1x, d12, v2x);
    float u2y = fmaf(-e1y, d12, v2y);
    float u2z = fmaf(-e1z, d12, v2z);
    float n2 = fast_sqrtf(fmaf(u2x, u2x, fmaf(u2y, u2y, u2z * u2z)));
    float inv2 = __fdividef(1.0f, n2 + 1e-8f);
    float e2x = u2x * inv2, e2y = u2y * inv2, e2z = u2z * inv2;
    float e3x = e1y * e2z - e1z * e2y;
    float e3y = e1z * e2x - e1x * e2z;
    float e3z = e1x * e2y - e1y * e2x;
    R[0] = e1x; R[1] = e1y; R[2] = e1z;
    R[3] = e2x; R[4] = e2y; R[5] = e2z;
    R[6] = e3x; R[7] = e3y; R[8] = e3z;
    t[0] = x2x; t[1] = x2y; t[2] = x2z;
}

__global__ void k_init() {
    g_K = 0;
    g_S[0] = 0.0;
    g_S[1] = 0.0;
}

// One warp per row, FULL scan with int4 loads (MLP=16, no serial early-exit):
// find the smallest j > row with m[row][j] != 0.
__global__ void k_pairs(const int* __restrict__ m, int L) {
    int row = (blockIdx.x * blockDim.x + threadIdx.x) >> 5;
    int lane = threadIdx.x & 31;
    if (row >= L) return;
    const int* rp = m + (long long)row * L;
    const int4* r4 = (const int4*)rp;
    int n4 = L >> 2;
    int best = 0x7fffffff;
    for (int t = lane; t < n4; t += 32) {
        int4 v = __ldg(&r4[t]);
        int c = t << 2;
        if (v.x != 0 && c     > row) best = min(best, c);
        if (v.y != 0 && c + 1 > row) best = min(best, c + 1);
        if (v.z != 0 && c + 2 > row) best = min(best, c + 2);
        if (v.w != 0 && c + 3 > row) best = min(best, c + 3);
    }
    for (int j = (n4 << 2) + lane; j < L; j += 32) {
        if (rp[j] != 0 && j > row) best = min(best, j);
    }
    #pragma unroll
    for (int o = 16; o; o >>= 1) best = min(best, __shfl_xor_sync(0xffffffffu, best, o));
    if (lane == 0 && best != 0x7fffffff) {
        int s = atomicAdd(&g_K, 1);
        g_pairs[2 * s]     = row;
        g_pairs[2 * s + 1] = best;
    }
}

// Build precomposed RELATIVE-frame table. dist = ||x - (M y + d)|| with
// M = Rp^T Rt, d = tp - M tt (Rp ~orthogonal; err ~1e-4 rel, tol 1e-3).
// Record: nM[9] (= -M), nd[3] (= M tt - tp = -d), clamp^2, pad[3]  (stride 16)
__global__ void k_frames(const float* __restrict__ coor,
                         const float* __restrict__ prot,
                         const float* __restrict__ ptran,
                         const float* __restrict__ target, int L) {
    int t = blockIdx.x * blockDim.x + threadIdx.x;
    int K = g_K;
    if (t >= 2 * L + K) return;

    float Rp[9], tp[3], Rt[9], tt[3], clampv;
    if (t < L) {
        #pragma unroll
        for (int i = 0; i < 9; i++) Rp[i] = prot[t * 9 + i];
        tp[0] = ptran[t * 3 + 0];
        tp[1] = ptran[t * 3 + 1];
        tp[2] = ptran[t * 3 + 2];
        rigid3(target + t * 9, Rt, tt);
        clampv = 40.0f;
    } else if (t < 2 * L) {
        int i = t - L;
        rigid3(coor + i * 9, Rp, tp);
        rigid3(target + i * 9, Rt, tt);
        clampv = 5.0f;
    } else {
        int k = t - 2 * L;
        int i = g_pairs[2 * k], j = g_pairs[2 * k + 1];
        float mc[9], mt[9];
        #pragma unroll
        for (int q = 0; q < 9; q++) {
            mc[q] = 0.5f * (coor[i * 9 + q] + coor[j * 9 + q]);
            mt[q] = 0.5f * (target[i * 9 + q] + target[j * 9 + q]);
        }
        rigid3(mc, Rp, tp);
        rigid3(mt, Rt, tt);
        clampv = 5.0f;
    }

    // M = Rp^T Rt :  M[i][j] = sum_k Rp[k][i] * Rt[k][j]
    float M[9];
    #pragma unroll
    for (int i = 0; i < 3; i++)
        #pragma unroll
        for (int j = 0; j < 3; j++)
            M[3 * i + j] = fmaf(Rp[i], Rt[j],
                           fmaf(Rp[3 + i], Rt[3 + j],
                                Rp[6 + i] * Rt[6 + j]));

    float* o = g_frames + t * FR_STRIDE;
    #pragma unroll
    for (int i = 0; i < 9; i++) o[i] = -M[i];
    #pragma unroll
    for (int k = 0; k < 3; k++) {
        // nd = M tt - tp
        o[9 + k] = fmaf(M[3 * k], tt[0],
                   fmaf(M[3 * k + 1], tt[1],
                   fmaf(M[3 * k + 2], tt[2], -tp[k])));
    }
    o[12] = clampv * clampv;
    o[13] = 0.0f; o[14] = 0.0f; o[15] = 0.0f;
}

// Main FAPE kernel, packed f32x2 over point-PAIRS with relative-frame math:
//   e = x + (nM*y + nd);  dist2 = e.e + ep
// smem tile pair-interleaved: sp[q*12 + d*2 + lane], d in {x0,x1,x2,y0,y1,y2}.
__global__ void __launch_bounds__(128) k_main(const float* __restrict__ coor,
                                              const float* __restrict__ target, int L) {
    __shared__ __align__(16) float sp[TILE * 6];
    __shared__ float r0s[4], r1s[4];

    int K = g_K;
    int nframes = 2 * L + K;
    if (blockIdx.y * 128 >= nframes) return;
    int frame = blockIdx.y * 128 + threadIdx.x;
    int P = 3 * L;
    int p0 = blockIdx.x * TILE;
    int npt = P - p0;
    if (npt > TILE) npt = TILE;

    for (int idx = threadIdx.x; idx < TILE * 3; idx += 128) {
        float vc = 0.0f, vt = 0.0f;
        if (idx < npt * 3) {
            vc = coor[p0 * 3 + idx];
            vt = target[p0 * 3 + idx];
        }
        int p = idx / 3, d = idx - 3 * p;
        int q = p >> 1, ln = p & 1;
        sp[q * 12 + d * 2 + ln]       = vc;
        sp[q * 12 + (d + 3) * 2 + ln] = vt;
    }
    __syncthreads();

    float acc = 0.0f;
    if (frame < nframes) {
        const float4* fr = (const float4*)(g_frames + frame * FR_STRIDE);
        float4 f0 = fr[0], f1 = fr[1], f2 = fr[2], f3 = fr[3];
        // nM rows, nd, csq
        u64 M0 = pk2(f0.x, f0.x), M1 = pk2(f0.y, f0.y), M2 = pk2(f0.z, f0.z);
        u64 M3 = pk2(f0.w, f0.w), M4 = pk2(f1.x, f1.x), M5 = pk2(f1.y, f1.y);
        u64 M6 = pk2(f1.z, f1.z), M7 = pk2(f1.w, f1.w), M8 = pk2(f2.x, f2.x);
        u64 D0 = pk2(f2.y, f2.y), D1 = pk2(f2.z, f2.z), D2 = pk2(f2.w, f2.w);
        float csq = f3.x;
        u64 EP2 = pk2(0.001f, 0.001f);

        const ulonglong2* sv = (const ulonglong2*)sp;
        int nq = npt >> 1;
        float accL = 0.0f, accH = 0.0f;
        #pragma unroll 8
        for (int q = 0; q < nq; ++q) {
            ulonglong2 v0 = sv[q * 3 + 0];   // {X0, X1}
            ulonglong2 v1 = sv[q * 3 + 1];   // {X2, Y0}
            ulonglong2 v2 = sv[q * 3 + 2];   // {Y1, Y2}
            u64 w0 = fma2(M0, v1.y, fma2(M1, v2.x, fma2(M2, v2.y, D0)));
            u64 w1 = fma2(M3, v1.y, fma2(M4, v2.x, fma2(M5, v2.y, D1)));
            u64 w2 = fma2(M6, v1.y, fma2(M7, v2.x, fma2(M8, v2.y, D2)));
            u64 e0 = add2(v0.x, w0);
            u64 e1 = add2(v0.y, w1);
            u64 e2 = add2(v1.x, w2);
            u64 S = fma2(e0, e0, fma2(e1, e1, fma2(e2, e2, EP2)));
            float sl, sh;
            upk2(sl, sh, S);
            sl = fminf(sl, csq);
            sh = fminf(sh, csq);
            accL += fast_sqrtf(sl);
            accH += fast_sqrtf(sh);
        }
        acc = accL + accH;
        if (npt & 1) {   // scalar tail point (never for P%TILE==0)
            const float* pt = sp + (nq * 12);
            float x0 = pt[0], x1 = pt[2], x2 = pt[4], y0 = pt[6], y1 = pt[8], y2 = pt[10];
            float w0 = fmaf(f0.x, y0, fmaf(f0.y, y1, fmaf(f0.z, y2, f2.y)));
            float w1 = fmaf(f0.w, y0, fmaf(f1.x, y1, fmaf(f1.y, y2, f2.z)));
            float w2 = fmaf(f1.z, y0, fmaf(f1.w, y1, fmaf(f2.x, y2, f2.w)));
            float e0 = x0 + w0, e1 = x1 + w1, e2 = x2 + w2;
            float s = fmaf(e0, e0, fmaf(e1, e1, fmaf(e2, e2, 0.001f)));
            acc += fast_sqrtf(fminf(s, csq));
        }
    }

    float acc0 = (frame < L) ? acc : 0.0f;
    float acc1 = (frame < L) ? 0.0f : acc;
    #pragma unroll
    for (int o = 16; o; o >>= 1) {
        acc0 += __shfl_down_sync(0xffffffffu, acc0, o);
        acc1 += __shfl_down_sync(0xffffffffu, acc1, o);
    }
    int w = threadIdx.x >> 5, l = threadIdx.x & 31;
    if (l == 0) { r0s[w] = acc0; r1s[w] = acc1; }
    __syncthreads();
    if (threadIdx.x == 0) {
        float s0 = r0s[0] + r0s[1] + r0s[2] + r0s[3];
        float s1 = r1s[0] + r1s[1] + r1s[2] + r1s[3];
        if (s0 != 0.0f) atomicAdd(&g_S[0], (double)s0);
        if (s1 != 0.0f) atomicAdd(&g_S[1], (double)s1);
    }
}

__global__ void k_final(float* out, int L) {
    double P = 3.0 * (double)L;
    double res = g_S[0] / ((double)L * P);
    int K = g_K;
    if (K > 0) res += g_S[1] / ((double)(L + K) * P);
    out[0] = (float)(res * 0.1);
}

extern "C" void kernel_launch(void* const* d_in, const int* in_sizes, int n_in,
                              void* d_out, int out_size) {
    const float* coor   = (const float*)d_in[0];
    const float* prot   = (const float*)d_in[1];
    const float* ptran  = (const float*)d_in[2];
    const float* target = (const float*)d_in[3];
    const int*   matrix = (const int*)d_in[4];

    int L = in_sizes[0] / 9;
    int P = 3 * L;
    int maxFrames = 3 * L;   // 2L + K, K <= L

    k_init<<<1, 1>>>();
    k_pairs<<<(L * 32 + 255) / 256, 256>>>(matrix, L);
    k_frames<<<(maxFrames + 255) / 256, 256>>>(coor, prot, ptran, target, L);
    dim3 grid((P + TILE - 1) / TILE, (maxFrames + 127) / 128);
    k_main<<<grid, 128>>>(coor, target, L);
    k_final<<<1, 1>>>((float*)d_out, L);
}

// round 4
// speedup vs baseline: 1.9115x; 1.1037x over previous
#include <cuda_runtime.h>

#define MAXL 2048
#define TILE 128
#define FR_STRIDE 16

typedef unsigned long long u64;

// Scratch (no allocations allowed): frame table, pair list, accumulators.
// NOTE: zero-initialized at module load; k_final resets them after use so every
// kernel_launch invocation starts from the same (zeroed) state.
__device__ float  g_frames[3 * MAXL * FR_STRIDE];
__device__ int    g_pairs[2 * MAXL];
__device__ int    g_K;
__device__ double g_S[2];

__device__ __forceinline__ float fast_sqrtf(float x) {
    float r;
    asm("sqrt.approx.f32 %0, %1;" : "=f"(r) : "f"(x));
    return r;
}

// ---- packed f32x2 helpers (FFMA2/FADD2 only reachable via PTX) ----
__device__ __forceinline__ u64 pk2(float lo, float hi) {
    u64 r;
    asm("mov.b64 %0, {%1, %2};" : "=l"(r) : "f"(lo), "f"(hi));
    return r;
}
__device__ __forceinline__ void upk2(float& lo, float& hi, u64 v) {
    asm("mov.b64 {%0, %1}, %2;" : "=f"(lo), "=f"(hi) : "l"(v));
}
__device__ __forceinline__ u64 fma2(u64 a, u64 b, u64 c) {
    u64 d;
    asm("fma.rn.f32x2 %0, %1, %2, %3;" : "=l"(d) : "l"(a), "l"(b), "l"(c));
    return d;
}
__device__ __forceinline__ u64 add2(u64 a, u64 b) {
    u64 d;
    asm("add.rn.f32x2 %0, %1, %2;" : "=l"(d) : "l"(a), "l"(b));
    return d;
}

// rigid_from_3points: a = 9 floats (x1,x2,x3 atoms). R row-major (rows e1,e2,e3), t = x2.
__device__ __forceinline__ void rigid3(const float* __restrict__ a, float R[9], float t[3]) {
    float x1x = a[0], x1y = a[1], x1z = a[2];
    float x2x = a[3], x2y = a[4], x2z = a[5];
    float x3x = a[6], x3y = a[7], x3z = a[8];
    float v1x = x3x - x2x, v1y = x3y - x2y, v1z = x3z - x2z;
    float v2x = x1x - x2x, v2y = x1y - x2y, v2z = x1z - x2z;
    float n1 = fast_sqrtf(fmaf(v1x, v1x, fmaf(v1y, v1y, v1z * v1z)));
    float inv1 = __fdividef(1.0f, n1 + 0.001f);
    float e1x = v1x * inv1, e1y = v1y * inv1, e1z = v1z * inv1;
    float d12 = fmaf(e1x, v2x, fmaf(e1y, v2y, e1z * v2z));
    float u2x = fmaf(-e1x, d12, v2x);
    float u2y = fmaf(-e1y, d12, v2y);
    float u2z = fmaf(-e1z, d12, v2z);
    float n2 = fast_sqrtf(fmaf(u2x, u2x, fmaf(u2y, u2y, u2z * u2z)));
    float inv2 = __fdividef(1.0f, n2 + 1e-8f);
    float e2x = u2x * inv2, e2y = u2y * inv2, e2z = u2z * inv2;
    float e3x = e1y * e2z - e1z * e2y;
    float e3y = e1z * e2x - e1x * e2z;
    float e3z = e1x * e2y - e1y * e2x;
    R[0] = e1x; R[1] = e1y; R[2] = e1z;
    R[3] = e2x; R[4] = e2y; R[5] = e2z;
    R[6] = e3x; R[7] = e3y; R[8] = e3z;
    t[0] = x2x; t[1] = x2y; t[2] = x2z;
}

// One warp per row, FULL scan with int4 loads (MLP=16, no serial early-exit):
// find the smallest j > row with m[row][j] != 0.
__global__ void k_pairs(const int* __restrict__ m, int L) {
    int row = (blockIdx.x * blockDim.x + threadIdx.x) >> 5;
    int lane = threadIdx.x & 31;
    if (row >= L) return;
    const int* rp = m + (long long)row * L;
    const int4* r4 = (const int4*)rp;
    int n4 = L >> 2;
    int best = 0x7fffffff;
    for (int t = lane; t < n4; t += 32) {
        int4 v = __ldg(&r4[t]);
        int c = t << 2;
        if (v.x != 0 && c     > row) best = min(best, c);
        if (v.y != 0 && c + 1 > row) best = min(best, c + 1);
        if (v.z != 0 && c + 2 > row) best = min(best, c + 2);
        if (v.w != 0 && c + 3 > row) best = min(best, c + 3);
    }
    for (int j = (n4 << 2) + lane; j < L; j += 32) {
        if (rp[j] != 0 && j > row) best = min(best, j);
    }
    #pragma unroll
    for (int o = 16; o; o >>= 1) best = min(best, __shfl_xor_sync(0xffffffffu, best, o));
    if (lane == 0 && best != 0x7fffffff) {
        int s = atomicAdd(&g_K, 1);
        g_pairs[2 * s]     = row;
        g_pairs[2 * s + 1] = best;
    }
}

// Build precomposed RELATIVE-frame table. dist = ||x - (M y + d)|| with
// M = Rp^T Rt, d = tp - M tt (Rp ~orthogonal; err ~1e-4 rel, tol 1e-3).
// Record: nM[9] (= -M), nd[3] (= M tt - tp = -d), clamp^2, pad[3]  (stride 16)
__global__ void k_frames(const float* __restrict__ coor,
                         const float* __restrict__ prot,
                         const float* __restrict__ ptran,
                         const float* __restrict__ target, int L) {
    int t = blockIdx.x * blockDim.x + threadIdx.x;
    int K = g_K;
    if (t >= 2 * L + K) return;

    float Rp[9], tp[3], Rt[9], tt[3], clampv;
    if (t < L) {
        #pragma unroll
        for (int i = 0; i < 9; i++) Rp[i] = prot[t * 9 + i];
        tp[0] = ptran[t * 3 + 0];
        tp[1] = ptran[t * 3 + 1];
        tp[2] = ptran[t * 3 + 2];
        rigid3(target + t * 9, Rt, tt);
        clampv = 40.0f;
    } else if (t < 2 * L) {
        int i = t - L;
        rigid3(coor + i * 9, Rp, tp);
        rigid3(target + i * 9, Rt, tt);
        clampv = 5.0f;
    } else {
        int k = t - 2 * L;
        int i = g_pairs[2 * k], j = g_pairs[2 * k + 1];
        float mc[9], mt[9];
        #pragma unroll
        for (int q = 0; q < 9; q++) {
            mc[q] = 0.5f * (coor[i * 9 + q] + coor[j * 9 + q]);
            mt[q] = 0.5f * (target[i * 9 + q] + target[j * 9 + q]);
        }
        rigid3(mc, Rp, tp);
        rigid3(mt, Rt, tt);
        clampv = 5.0f;
    }

    // M = Rp^T Rt :  M[i][j] = sum_k Rp[k][i] * Rt[k][j]
    float M[9];
    #pragma unroll
    for (int i = 0; i < 3; i++)
        #pragma unroll
        for (int j = 0; j < 3; j++)
            M[3 * i + j] = fmaf(Rp[i], Rt[j],
                           fmaf(Rp[3 + i], Rt[3 + j],
                                Rp[6 + i] * Rt[6 + j]));

    float* o = g_frames + t * FR_STRIDE;
    #pragma unroll
    for (int i = 0; i < 9; i++) o[i] = -M[i];
    #pragma unroll
    for (int k = 0; k < 3; k++) {
        o[9 + k] = fmaf(M[3 * k], tt[0],
                   fmaf(M[3 * k + 1], tt[1],
                   fmaf(M[3 * k + 2], tt[2], -tp[k])));   // nd = M tt - tp
    }
    o[12] = clampv * clampv;
    o[13] = 0.0f; o[14] = 0.0f; o[15] = 0.0f;
}

// Main FAPE kernel, packed f32x2 over point-PAIRS with relative-frame math:
//   e = x + (nM*y + nd);  dist2 = e.e + ep
// smem tile pair-interleaved: sp[q*12 + d*2 + lane], d in {x0,x1,x2,y0,y1,y2}.
__global__ void __launch_bounds__(128) k_main(const float* __restrict__ coor,
                                              const float* __restrict__ target, int L) {
    __shared__ __align__(16) float sp[TILE * 6];
    __shared__ float r0s[4], r1s[4];

    int K = g_K;
    int nframes = 2 * L + K;
    if (blockIdx.y * 128 >= nframes) return;
    int frame = blockIdx.y * 128 + threadIdx.x;
    int P = 3 * L;
    int p0 = blockIdx.x * TILE;
    int npt = P - p0;
    if (npt > TILE) npt = TILE;

    for (int idx = threadIdx.x; idx < TILE * 3; idx += 128) {
        float vc = 0.0f, vt = 0.0f;
        if (idx < npt * 3) {
            vc = coor[p0 * 3 + idx];
            vt = target[p0 * 3 + idx];
        }
        int p = idx / 3, d = idx - 3 * p;
        int q = p >> 1, ln = p & 1;
        sp[q * 12 + d * 2 + ln]       = vc;
        sp[q * 12 + (d + 3) * 2 + ln] = vt;
    }
    __syncthreads();

    float acc = 0.0f;
    if (frame < nframes) {
        const float4* fr = (const float4*)(g_frames + frame * FR_STRIDE);
        float4 f0 = fr[0], f1 = fr[1], f2 = fr[2], f3 = fr[3];
        u64 M0 = pk2(f0.x, f0.x), M1 = pk2(f0.y, f0.y), M2 = pk2(f0.z, f0.z);
        u64 M3 = pk2(f0.w, f0.w), M4 = pk2(f1.x, f1.x), M5 = pk2(f1.y, f1.y);
        u64 M6 = pk2(f1.z, f1.z), M7 = pk2(f1.w, f1.w), M8 = pk2(f2.x, f2.x);
        u64 D0 = pk2(f2.y, f2.y), D1 = pk2(f2.z, f2.z), D2 = pk2(f2.w, f2.w);
        float csq = f3.x;
        u64 EP2 = pk2(0.001f, 0.001f);

        const ulonglong2* sv = (const ulonglong2*)sp;
        int nq = npt >> 1;
        float accL = 0.0f, accH = 0.0f;
        #pragma unroll 8
        for (int q = 0; q < nq; ++q) {
            ulonglong2 v0 = sv[q * 3 + 0];   // {X0, X1}
            ulonglong2 v1 = sv[q * 3 + 1];   // {X2, Y0}
            ulonglong2 v2 = sv[q * 3 + 2];   // {Y1, Y2}
            u64 w0 = fma2(M0, v1.y, fma2(M1, v2.x, fma2(M2, v2.y, D0)));
            u64 w1 = fma2(M3, v1.y, fma2(M4, v2.x, fma2(M5, v2.y, D1)));
            u64 w2 = fma2(M6, v1.y, fma2(M7, v2.x, fma2(M8, v2.y, D2)));
            u64 e0 = add2(v0.x, w0);
            u64 e1 = add2(v0.y, w1);
            u64 e2 = add2(v1.x, w2);
            u64 S = fma2(e0, e0, fma2(e1, e1, fma2(e2, e2, EP2)));
            float sl, sh;
            upk2(sl, sh, S);
            sl = fminf(sl, csq);
            sh = fminf(sh, csq);
            accL += fast_sqrtf(sl);
            accH += fast_sqrtf(sh);
        }
        acc = accL + accH;
        if (npt & 1) {   // scalar tail point (never for P%TILE==0)
            const float* pt = sp + (nq * 12);
            float x0 = pt[0], x1 = pt[2], x2 = pt[4], y0 = pt[6], y1 = pt[8], y2 = pt[10];
            float w0 = fmaf(f0.x, y0, fmaf(f0.y, y1, fmaf(f0.z, y2, f2.y)));
            float w1 = fmaf(f0.w, y0, fmaf(f1.x, y1, fmaf(f1.y, y2, f2.z)));
            float w2 = fmaf(f1.z, y0, fmaf(f1.w, y1, fmaf(f2.x, y2, f2.w)));
            float e0 = x0 + w0, e1 = x1 + w1, e2 = x2 + w2;
            float s = fmaf(e0, e0, fmaf(e1, e1, fmaf(e2, e2, 0.001f)));
            acc += fast_sqrtf(fminf(s, csq));
        }
    }

    float acc0 = (frame < L) ? acc : 0.0f;
    float acc1 = (frame < L) ? 0.0f : acc;
    #pragma unroll
    for (int o = 16; o; o >>= 1) {
        acc0 += __shfl_down_sync(0xffffffffu, acc0, o);
        acc1 += __shfl_down_sync(0xffffffffu, acc1, o);
    }
    int w = threadIdx.x >> 5, l = threadIdx.x & 31;
    if (l == 0) { r0s[w] = acc0; r1s[w] = acc1; }
    __syncthreads();
    if (threadIdx.x == 0) {
        float s0 = r0s[0] + r0s[1] + r0s[2] + r0s[3];
        float s1 = r1s[0] + r1s[1] + r1s[2] + r1s[3];
        if (s0 != 0.0f) atomicAdd(&g_S[0], (double)s0);
        if (s1 != 0.0f) atomicAdd(&g_S[1], (double)s1);
    }
}

// Emits result AND resets scratch state so the next invocation starts zeroed
// (replaces the separate k_init launch).
__global__ void k_final(float* out, int L) {
    double P = 3.0 * (double)L;
    double res = g_S[0] / ((double)L * P);
    int K = g_K;
    if (K > 0) res += g_S[1] / ((double)(L + K) * P);
    out[0] = (float)(res * 0.1);
    g_K = 0;
    g_S[0] = 0.0;
    g_S[1] = 0.0;
}

extern "C" void kernel_launch(void* const* d_in, const int* in_sizes, int n_in,
                              void* d_out, int out_size) {
    const float* coor   = (const float*)d_in[0];
    const float* prot   = (const float*)d_in[1];
    const float* ptran  = (const float*)d_in[2];
    const float* target = (const float*)d_in[3];
    const int*   matrix = (const int*)d_in[4];

    int L = in_sizes[0] / 9;
    int P = 3 * L;
    int maxFrames = 3 * L;   // 2L + K, K <= L

    k_pairs<<<(L * 32 + 255) / 256, 256>>>(matrix, L);
    k_frames<<<(maxFrames + 255) / 256, 256>>>(coor, prot, ptran, target, L);
    dim3 grid((P + TILE - 1) / TILE, (maxFrames + 127) / 128);
    k_main<<<grid, 128>>>(coor, target, L);
    k_final<<<1, 1>>>((float*)d_out, L);
}

// round 5
// speedup vs baseline: 2.0836x; 1.0901x over previous
#include <cuda_runtime.h>

#define MAXL 2048
#define TILE 128
#define FR_STRIDE 16

typedef unsigned long long u64;

// Scratch (no allocations allowed). Zero-init at load; the LAST k_main block
// resets everything after emitting the result, so each invocation starts zeroed.
__device__ float    g_frames[3 * MAXL * FR_STRIDE];
__device__ int      g_K;
__device__ double   g_S[2];
__device__ unsigned g_done;

__device__ __forceinline__ float fast_sqrtf(float x) {
    float r;
    asm("sqrt.approx.f32 %0, %1;" : "=f"(r) : "f"(x));
    return r;
}

// ---- packed f32x2 helpers (FFMA2/FADD2 only reachable via PTX) ----
__device__ __forceinline__ u64 pk2(float lo, float hi) {
    u64 r;
    asm("mov.b64 %0, {%1, %2};" : "=l"(r) : "f"(lo), "f"(hi));
    return r;
}
__device__ __forceinline__ void upk2(float& lo, float& hi, u64 v) {
    asm("mov.b64 {%0, %1}, %2;" : "=f"(lo), "=f"(hi) : "l"(v));
}
__device__ __forceinline__ u64 fma2(u64 a, u64 b, u64 c) {
    u64 d;
    asm("fma.rn.f32x2 %0, %1, %2, %3;" : "=l"(d) : "l"(a), "l"(b), "l"(c));
    return d;
}
__device__ __forceinline__ u64 add2(u64 a, u64 b) {
    u64 d;
    asm("add.rn.f32x2 %0, %1, %2;" : "=l"(d) : "l"(a), "l"(b));
    return d;
}

// rigid_from_3points: a = 9 floats (x1,x2,x3). R rows e1,e2,e3; t = x2.
__device__ __forceinline__ void rigid3(const float* __restrict__ a, float R[9], float t[3]) {
    float v1x = a[6] - a[3], v1y = a[7] - a[4], v1z = a[8] - a[5];
    float v2x = a[0] - a[3], v2y = a[1] - a[4], v2z = a[2] - a[5];
    float n1 = fast_sqrtf(fmaf(v1x, v1x, fmaf(v1y, v1y, v1z * v1z)));
    float inv1 = __fdividef(1.0f, n1 + 0.001f);
    float e1x = v1x * inv1, e1y = v1y * inv1, e1z = v1z * inv1;
    float d12 = fmaf(e1x, v2x, fmaf(e1y, v2y, e1z * v2z));
    float u2x = fmaf(-e1x, d12, v2x);
    float u2y = fmaf(-e1y, d12, v2y);
    float u2z = fmaf(-e1z, d12, v2z);
    float n2 = fast_sqrtf(fmaf(u2x, u2x, fmaf(u2y, u2y, u2z * u2z)));
    float inv2 = __fdividef(1.0f, n2 + 1e-8f);
    float e2x = u2x * inv2, e2y = u2y * inv2, e2z = u2z * inv2;
    R[0] = e1x; R[1] = e1y; R[2] = e1z;
    R[3] = e2x; R[4] = e2y; R[5] = e2z;
    R[6] = e1y * e2z - e1z * e2y;
    R[7] = e1z * e2x - e1x * e2z;
    R[8] = e1x * e2y - e1y * e2x;
    t[0] = a[3]; t[1] = a[4]; t[2] = a[5];
}

// Write relative-frame record t: nM[9] (= -Rp^T Rt), nd[3] (= M tt - tp), clamp^2.
__device__ __forceinline__ void write_frame(int t, const float Rp[9], const float tp[3],
                                            const float Rt[9], const float tt[3],
                                            float clampv) {
    float M[9];
    #pragma unroll
    for (int i = 0; i < 3; i++)
        #pragma unroll
        for (int j = 0; j < 3; j++)
            M[3 * i + j] = fmaf(Rp[i], Rt[j],
                           fmaf(Rp[3 + i], Rt[3 + j],
                                Rp[6 + i] * Rt[6 + j]));
    float* o = g_frames + t * FR_STRIDE;
    #pragma unroll
    for (int i = 0; i < 9; i++) o[i] = -M[i];
    #pragma unroll
    for (int k = 0; k < 3; k++)
        o[9 + k] = fmaf(M[3 * k], tt[0],
                   fmaf(M[3 * k + 1], tt[1],
                   fmaf(M[3 * k + 2], tt[2], -tp[k])));
    o[12] = clampv * clampv;
    o[13] = 0.0f; o[14] = 0.0f; o[15] = 0.0f;
}

// Fused prep kernel.
//  Part A (blocks [0, ablocks)): thread-per-frame for frames [0, 2L)
//     t in [0, L):  pred = given (p_rot,p_tran), true = rigid(target[i]), clamp 40
//     t in [L, 2L): pred = rigid(coor[i]),       true = rigid(target[i]), clamp 5
//  Part B (remaining blocks): warp-per-matrix-row. Warp scans row r with int4
//     loads (MLP high, no serial early-exit), finds first nz col j > r, and
//     lane 0 builds the midpoint pair frame into slot 2L + atomicAdd(g_K).
__global__ void __launch_bounds__(256) k_prep(const float* __restrict__ coor,
                                              const float* __restrict__ prot,
                                              const float* __restrict__ ptran,
                                              const float* __restrict__ target,
                                              const int* __restrict__ m,
                                              int L, int ablocks) {
    if ((int)blockIdx.x < ablocks) {
        int t = blockIdx.x * 256 + threadIdx.x;
        if (t >= 2 * L) return;
        float Rp[9], tp[3], Rt[9], tt[3];
        if (t < L) {
            #pragma unroll
            for (int i = 0; i < 9; i++) Rp[i] = prot[t * 9 + i];
            tp[0] = ptran[t * 3 + 0];
            tp[1] = ptran[t * 3 + 1];
            tp[2] = ptran[t * 3 + 2];
            rigid3(target + t * 9, Rt, tt);
            write_frame(t, Rp, tp, Rt, tt, 40.0f);
        } else {
            int i = t - L;
            rigid3(coor + i * 9, Rp, tp);
            rigid3(target + i * 9, Rt, tt);
            write_frame(t, Rp, tp, Rt, tt, 5.0f);
        }
    } else {
        int row = ((int)blockIdx.x - ablocks) * 8 + ((int)threadIdx.x >> 5);
        int lane = threadIdx.x & 31;
        if (row >= L) return;
        const int* rp = m + (long long)row * L;
        const int4* r4 = (const int4*)rp;
        int n4 = L >> 2;
        int best = 0x7fffffff;
        for (int t = lane; t < n4; t += 32) {
            int4 v = __ldg(&r4[t]);
            int c = t << 2;
            if (v.x != 0 && c     > row) best = min(best, c);
            if (v.y != 0 && c + 1 > row) best = min(best, c + 1);
            if (v.z != 0 && c + 2 > row) best = min(best, c + 2);
            if (v.w != 0 && c + 3 > row) best = min(best, c + 3);
        }
        for (int j = (n4 << 2) + lane; j < L; j += 32) {
            if (rp[j] != 0 && j > row) best = min(best, j);
        }
        #pragma unroll
        for (int o = 16; o; o >>= 1) best = min(best, __shfl_xor_sync(0xffffffffu, best, o));
        if (lane == 0 && best != 0x7fffffff) {
            int s = atomicAdd(&g_K, 1);
            int j = best;
            float mc[9], mt[9];
            #pragma unroll
            for (int q = 0; q < 9; q++) {
                mc[q] = 0.5f * (coor[row * 9 + q] + coor[j * 9 + q]);
                mt[q] = 0.5f * (target[row * 9 + q] + target[j * 9 + q]);
            }
            float Rp[9], tp[3], Rt[9], tt[3];
            rigid3(mc, Rp, tp);
            rigid3(mt, Rt, tt);
            write_frame(2 * L + s, Rp, tp, Rt, tt, 5.0f);
        }
    }
}

// Main FAPE kernel, packed f32x2 over point-PAIRS with relative-frame math:
//   e = x + (nM*y + nd);  dist2 = e.e + ep
// smem tile pair-interleaved: sp[q*12 + d*2 + lane], d in {x0,x1,x2,y0,y1,y2}.
// The LAST block to finish (threadfence-reduction pattern) emits the scalar
// output and resets all scratch state.
__global__ void __launch_bounds__(128) k_main(const float* __restrict__ coor,
                                              const float* __restrict__ target,
                                              int L, float* __restrict__ out,
                                              unsigned total) {
    __shared__ __align__(16) float sp[TILE * 6];
    __shared__ float r0s[4], r1s[4];

    int K = g_K;
    int nframes = 2 * L + K;

    if ((int)blockIdx.y * 128 < nframes) {
        int frame = blockIdx.y * 128 + threadIdx.x;
        int P = 3 * L;
        int p0 = blockIdx.x * TILE;
        int npt = P - p0;
        if (npt > TILE) npt = TILE;

        for (int idx = threadIdx.x; idx < TILE * 3; idx += 128) {
            float vc = 0.0f, vt = 0.0f;
            if (idx < npt * 3) {
                vc = coor[p0 * 3 + idx];
                vt = target[p0 * 3 + idx];
            }
            int p = idx / 3, d = idx - 3 * p;
            int q = p >> 1, ln = p & 1;
            sp[q * 12 + d * 2 + ln]       = vc;
            sp[q * 12 + (d + 3) * 2 + ln] = vt;
        }
        __syncthreads();

        float acc = 0.0f;
        if (frame < nframes) {
            const float4* fr = (const float4*)(g_frames + frame * FR_STRIDE);
            float4 f0 = fr[0], f1 = fr[1], f2 = fr[2], f3 = fr[3];
            u64 M0 = pk2(f0.x, f0.x), M1 = pk2(f0.y, f0.y), M2 = pk2(f0.z, f0.z);
            u64 M3 = pk2(f0.w, f0.w), M4 = pk2(f1.x, f1.x), M5 = pk2(f1.y, f1.y);
            u64 M6 = pk2(f1.z, f1.z), M7 = pk2(f1.w, f1.w), M8 = pk2(f2.x, f2.x);
            u64 D0 = pk2(f2.y, f2.y), D1 = pk2(f2.z, f2.z), D2 = pk2(f2.w, f2.w);
            float csq = f3.x;
            u64 EP2 = pk2(0.001f, 0.001f);

            const ulonglong2* sv = (const ulonglong2*)sp;
            int nq = npt >> 1;
            float accL = 0.0f, accH = 0.0f;
            #pragma unroll 8
            for (int q = 0; q < nq; ++q) {
                ulonglong2 v0 = sv[q * 3 + 0];   // {X0, X1}
                ulonglong2 v1 = sv[q * 3 + 1];   // {X2, Y0}
                ulonglong2 v2 = sv[q * 3 + 2];   // {Y1, Y2}
                u64 w0 = fma2(M0, v1.y, fma2(M1, v2.x, fma2(M2, v2.y, D0)));
                u64 w1 = fma2(M3, v1.y, fma2(M4, v2.x, fma2(M5, v2.y, D1)));
                u64 w2 = fma2(M6, v1.y, fma2(M7, v2.x, fma2(M8, v2.y, D2)));
                u64 e0 = add2(v0.x, w0);
                u64 e1 = add2(v0.y, w1);
                u64 e2 = add2(v1.x, w2);
                u64 S = fma2(e0, e0, fma2(e1, e1, fma2(e2, e2, EP2)));
                float sl, sh;
                upk2(sl, sh, S);
                sl = fminf(sl, csq);
                sh = fminf(sh, csq);
                accL += fast_sqrtf(sl);
                accH += fast_sqrtf(sh);
            }
            acc = accL + accH;
            if (npt & 1) {   // scalar tail (never taken for P % TILE == 0)
                const float* pt = sp + (nq * 12);
                float x0 = pt[0], x1 = pt[2], x2 = pt[4], y0 = pt[6], y1 = pt[8], y2 = pt[10];
                float w0 = fmaf(f0.x, y0, fmaf(f0.y, y1, fmaf(f0.z, y2, f2.y)));
                float w1 = fmaf(f0.w, y0, fmaf(f1.x, y1, fmaf(f1.y, y2, f2.z)));
                float w2 = fmaf(f1.z, y0, fmaf(f1.w, y1, fmaf(f2.x, y2, f2.w)));
                float e0 = x0 + w0, e1 = x1 + w1, e2 = x2 + w2;
                float s = fmaf(e0, e0, fmaf(e1, e1, fmaf(e2, e2, 0.001f)));
                acc += fast_sqrtf(fminf(s, csq));
            }
        }

        float acc0 = (frame < L) ? acc : 0.0f;
        float acc1 = (frame < L) ? 0.0f : acc;
        #pragma unroll
        for (int o = 16; o; o >>= 1) {
            acc0 += __shfl_down_sync(0xffffffffu, acc0, o);
            acc1 += __shfl_down_sync(0xffffffffu, acc1, o);
        }
        int w = threadIdx.x >> 5, l = threadIdx.x & 31;
        if (l == 0) { r0s[w] = acc0; r1s[w] = acc1; }
        __syncthreads();
        if (threadIdx.x == 0) {
            float s0 = r0s[0] + r0s[1] + r0s[2] + r0s[3];
            float s1 = r1s[0] + r1s[1] + r1s[2] + r1s[3];
            if (s0 != 0.0f) atomicAdd(&g_S[0], (double)s0);
            if (s1 != 0.0f) atomicAdd(&g_S[1], (double)s1);
        }
    }

    // Last-block finalize + scratch reset (threadfence-reduction pattern).
    __threadfence();
    if (threadIdx.x == 0) {
        unsigned t = atomicAdd(&g_done, 1u);
        if (t == total - 1) {
            double S0 = atomicAdd(&g_S[0], 0.0);
            double S1 = atomicAdd(&g_S[1], 0.0);
            double P = 3.0 * (double)L;
            double res = S0 / ((double)L * P);
            if (K > 0) res += S1 / ((double)(L + K) * P);
            out[0] = (float)(res * 0.1);
            g_done = 0;
            g_K = 0;
            g_S[0] = 0.0;
            g_S[1] = 0.0;
        }
    }
}

extern "C" void kernel_launch(void* const* d_in, const int* in_sizes, int n_in,
                              void* d_out, int out_size) {
    const float* coor   = (const float*)d_in[0];
    const float* prot   = (const float*)d_in[1];
    const float* ptran  = (const float*)d_in[2];
    const float* target = (const float*)d_in[3];
    const int*   matrix = (const int*)d_in[4];

    int L = in_sizes[0] / 9;
    int P = 3 * L;
    int maxFrames = 3 * L;   // 2L + K, K <= L

    int ablocks = (2 * L + 255) / 256;
    int bblocks = (L + 7) / 8;
    k_prep<<<ablocks + bblocks, 256>>>(coor, prot, ptran, target, matrix, L, ablocks);

    dim3 grid((P + TILE - 1) / TILE, (maxFrames + 127) / 128);
    unsigned total = grid.x * grid.y;
    k_main<<<grid, 128>>>(coor, target, L, (float*)d_out, total);
}